// round 15
// baseline (speedup 1.0000x reference)
#include <cuda_runtime.h>
#include <math.h>

// NeighborSearch: fixed-radius search, CSR float32 output [indices | splits].
// Exact fp semantics pinned by R14 oracle (variant v11, 7-digit match on two
// independent benched rel_errs):
//   n(p) = (x*x + z*z) + y*y
//   dot  = fma(qz,dz, fma(qy,dy, qx*dx))
//   sq   = fma(-2, dot, rn(nq + nd));  mask = sq <= T
//   T    = largest f32 with sqrt_rn(T) <= radius  (= sqrt(max(sq,0)) <= r)

#define MAXN   16384
#define CHUNKS 8
#define CHSZ   2048
#define QBLK   256

__device__ int   g_counts_c[CHUNKS * MAXN];
__device__ int   g_offsets[MAXN + 1];
__device__ float g_T;

// ------------------------------------------------------------- thresh -----
__global__ void thresh_kernel(const float* __restrict__ radius_ptr) {
    float r = 0.08f;
    if (radius_ptr != nullptr) {
        float f = *radius_ptr;
        if (f > 1e-6f && f < 1e3f) r = f;
    }
    float t = __fmul_rn(r, r);
    if (__fsqrt_rn(t) <= r) {
        for (int it = 0; it < 64; ++it) {
            float nt = nextafterf(t, 3.402823466e38f);
            if (__fsqrt_rn(nt) <= r) t = nt; else break;
        }
    } else {
        for (int it = 0; it < 64 && __fsqrt_rn(t) > r; ++it)
            t = nextafterf(t, 0.0f);
    }
    g_T = t;
}

// norm with the verified association: (x2 + z2) + y2
__device__ __forceinline__ float norm_ox(float x, float y, float z) {
    return __fadd_rn(__fadd_rn(__fmul_rn(x, x), __fmul_rn(z, z)),
                     __fmul_rn(y, y));
}

__device__ __forceinline__ void build_tile(float4* tile,
                                           const float* __restrict__ pts,
                                           int base, int n) {
    for (int j = threadIdx.x; j < n; j += blockDim.x) {
        float x = pts[3 * (base + j) + 0];
        float y = pts[3 * (base + j) + 1];
        float z = pts[3 * (base + j) + 2];
        tile[j] = make_float4(x, y, z, norm_ox(x, y, z));
    }
}

__device__ __forceinline__ float pair_sq(float qx, float qy, float qz, float qn,
                                         float4 d) {
    float dot = __fmaf_rn(qz, d.z, __fmaf_rn(qy, d.y, __fmul_rn(qx, d.x)));
    return __fmaf_rn(-2.0f, dot, __fadd_rn(qn, d.w));
}

// ---------------------------------------------------------------- count ---
__global__ void count_kernel(const float* __restrict__ data,
                             const float* __restrict__ queries,
                             int nq, int nd) {
    __shared__ float4 tile[CHSZ];
    const int chunk = (nd + CHUNKS - 1) / CHUNKS;
    const int c     = blockIdx.y;
    const int base  = c * chunk;
    const int n     = min(chunk, nd - base);
    const float T   = g_T;

    build_tile(tile, data, base, n);
    __syncthreads();

    int q = blockIdx.x * blockDim.x + threadIdx.x;
    if (q >= nq) return;

    float qx = queries[3 * q + 0];
    float qy = queries[3 * q + 1];
    float qz = queries[3 * q + 2];
    float qn = norm_ox(qx, qy, qz);

    int cnt = 0;
#pragma unroll 8
    for (int j = 0; j < n; ++j)
        cnt += (pair_sq(qx, qy, qz, qn, tile[j]) <= T) ? 1 : 0;
    g_counts_c[c * MAXN + q] = cnt;
}

// ---------------------------------------------------------------- scan ----
__global__ void scan_kernel(float* __restrict__ splits, int nq, int has_splits) {
    __shared__ int tsums[512];
    const int tid = threadIdx.x;
    const int PER = (MAXN + 511) / 512;  // 32
    const int start = tid * PER;

    int tot_q[(MAXN + 511) / 512];
    int mytot = 0;
    for (int i = 0; i < PER; ++i) {
        int q = start + i;
        int t = 0;
        if (q < nq) {
#pragma unroll
            for (int cc = 0; cc < CHUNKS; ++cc) t += g_counts_c[cc * MAXN + q];
        }
        tot_q[i] = t;
        mytot += t;
    }
    tsums[tid] = mytot;
    __syncthreads();

    for (int off = 1; off < 512; off <<= 1) {
        int v = (tid >= off) ? tsums[tid - off] : 0;
        __syncthreads();
        tsums[tid] += v;
        __syncthreads();
    }

    int run = (tid == 0) ? 0 : tsums[tid - 1];
    for (int i = 0; i < PER; ++i) {
        int q = start + i;
        if (q < nq) {
            g_offsets[q] = run;
            if (has_splits) splits[q] = (float)run;
            run += tot_q[i];
        }
    }
    if (tid == 511) {
        g_offsets[nq] = run;
        if (has_splits) splits[nq] = (float)run;
    }
}

// ---------------------------------------------------------------- fill ----
__global__ void fill_kernel(const float* __restrict__ data,
                            const float* __restrict__ queries,
                            int nq, int nd,
                            float* __restrict__ idx, int cap) {
    __shared__ float4 tile[CHSZ];
    const int chunk = (nd + CHUNKS - 1) / CHUNKS;
    const int c     = blockIdx.y;
    const int base  = c * chunk;
    const int n     = min(chunk, nd - base);
    const float T   = g_T;

    build_tile(tile, data, base, n);
    __syncthreads();

    int q = blockIdx.x * blockDim.x + threadIdx.x;
    if (q >= nq) return;

    float qx = queries[3 * q + 0];
    float qy = queries[3 * q + 1];
    float qz = queries[3 * q + 2];
    float qn = norm_ox(qx, qy, qz);

    int w = g_offsets[q];
    for (int cc = 0; cc < c; ++cc) w += g_counts_c[cc * MAXN + q];

    for (int j = 0; j < n; ++j) {
        if (pair_sq(qx, qy, qz, qn, tile[j]) <= T) {
            if (w >= 0 && w < cap) idx[w] = (float)(base + j);
            ++w;
        }
    }
}

// -------------------------------------------------------------- launch ----
extern "C" void kernel_launch(void* const* d_in, const int* in_sizes, int n_in,
                              void* d_out, int out_size) {
    const float* data    = (const float*)d_in[0];
    const float* queries = (const float*)d_in[1];
    const float* radius  = (n_in >= 3 && in_sizes[2] >= 1) ? (const float*)d_in[2]
                                                           : nullptr;
    const int nd = in_sizes[0] / 3;
    const int nq = in_sizes[1] / 3;
    if (nd <= 0 || nq <= 0 || nd > MAXN || nq > MAXN) return;

    float* out = (float*)d_out;
    // layout: [ neighbors_index (out_size - nq - 1) | splits (nq+1) ]
    const int has_splits = (out_size >= nq + 1) ? 1 : 0;
    float* splits = has_splits ? (out + (out_size - (nq + 1))) : out;
    const int cap = has_splits ? (out_size - (nq + 1)) : out_size;

    dim3 gridc((nq + QBLK - 1) / QBLK, CHUNKS);

    thresh_kernel<<<1, 1>>>(radius);
    count_kernel <<<gridc, QBLK>>>(data, queries, nq, nd);
    scan_kernel  <<<1, 512>>>(splits, nq, has_splits);
    fill_kernel  <<<gridc, QBLK>>>(data, queries, nq, nd, out, cap);
}

// round 16
// speedup vs baseline: 1.7282x; 1.7282x over previous
#include <cuda_runtime.h>
#include <math.h>

// NeighborSearch: fixed-radius search, CSR float32 output [indices | splits].
// Exact fp semantics (pinned R14, verified rel_err=0.0 in R15):
//   n(p) = (x*x + z*z) + y*y
//   dot  = fma(qz,dz, fma(qy,dy, qx*dx))
//   sq   = fma(-2, dot, rn(nq + nd));  mask = sq <= T
//   T    = largest f32 with sqrt_rn(T) <= radius
// R16 optimization: count emits a bitmask (L2-resident, 33.5 MB) so fill is a
// bit-scan instead of a second 268M-pair evaluation; CHUNKS=16 for occupancy;
// per-query totals reduced in a dedicated kernel to unblock the scan.

#define MAXN   16384
#define CHUNKS 16
#define CHSZ   1024                 // MAXN / CHUNKS
#define WPC    (CHSZ / 32)          // 32 mask words per chunk
#define NWORDS (MAXN / 32)          // 512 words per query
#define QBLK   256

__device__ unsigned g_mask[NWORDS * MAXN];     // [word][q], 33.5 MB
__device__ int      g_counts_c[CHUNKS * MAXN];
__device__ int      g_qtot[MAXN];
__device__ int      g_offsets[MAXN + 1];
__device__ float    g_T;

// ------------------------------------------------------------- thresh -----
__global__ void thresh_kernel(const float* __restrict__ radius_ptr) {
    float r = 0.08f;
    if (radius_ptr != nullptr) {
        float f = *radius_ptr;
        if (f > 1e-6f && f < 1e3f) r = f;
    }
    float t = __fmul_rn(r, r);
    if (__fsqrt_rn(t) <= r) {
        for (int it = 0; it < 64; ++it) {
            float nt = nextafterf(t, 3.402823466e38f);
            if (__fsqrt_rn(nt) <= r) t = nt; else break;
        }
    } else {
        for (int it = 0; it < 64 && __fsqrt_rn(t) > r; ++it)
            t = nextafterf(t, 0.0f);
    }
    g_T = t;
}

__device__ __forceinline__ float norm_ox(float x, float y, float z) {
    return __fadd_rn(__fadd_rn(__fmul_rn(x, x), __fmul_rn(z, z)),
                     __fmul_rn(y, y));
}

__device__ __forceinline__ float pair_sq(float qx, float qy, float qz, float qn,
                                         float4 d) {
    float dot = __fmaf_rn(qz, d.z, __fmaf_rn(qy, d.y, __fmul_rn(qx, d.x)));
    return __fmaf_rn(-2.0f, dot, __fadd_rn(qn, d.w));
}

// ---------------------------------------------------------------- count ---
// Emits the pair bitmask + per-(chunk,query) counts.
__global__ void count_kernel(const float* __restrict__ data,
                             const float* __restrict__ queries,
                             int nq, int nd) {
    __shared__ float4 tile[CHSZ];
    const int c    = blockIdx.y;
    const int base = c * CHSZ;
    const int n    = min(CHSZ, nd - base);
    const float T  = g_T;

    for (int j = threadIdx.x; j < n; j += blockDim.x) {
        float x = data[3 * (base + j) + 0];
        float y = data[3 * (base + j) + 1];
        float z = data[3 * (base + j) + 2];
        tile[j] = make_float4(x, y, z, norm_ox(x, y, z));
    }
    __syncthreads();

    int q = blockIdx.x * blockDim.x + threadIdx.x;
    if (q >= nq) return;

    float qx = queries[3 * q + 0];
    float qy = queries[3 * q + 1];
    float qz = queries[3 * q + 2];
    float qn = norm_ox(qx, qy, qz);

    int cnt = 0;
    for (int w = 0; w < WPC; ++w) {
        unsigned word = 0;
#pragma unroll
        for (int b = 0; b < 32; ++b) {
            int j = w * 32 + b;
            bool hit = (j < n) && (pair_sq(qx, qy, qz, qn, tile[j]) <= T);
            word |= (hit ? (1u << b) : 0u);
        }
        g_mask[(c * WPC + w) * nq + q] = word;   // coalesced across q
        cnt += __popc(word);
    }
    g_counts_c[c * MAXN + q] = cnt;
}

// --------------------------------------------------------------- reduce ---
__global__ void reduce_kernel(int nq) {
    int q = blockIdx.x * blockDim.x + threadIdx.x;
    if (q >= nq) return;
    int t = 0;
#pragma unroll
    for (int cc = 0; cc < CHUNKS; ++cc) t += g_counts_c[cc * MAXN + q];
    g_qtot[q] = t;
}

// ---------------------------------------------------------------- scan ----
__global__ void scan_kernel(float* __restrict__ splits, int nq, int has_splits) {
    __shared__ int tsums[512];
    const int tid = threadIdx.x;
    const int PER = (MAXN + 511) / 512;  // 32
    const int start = tid * PER;

    int tot_q[(MAXN + 511) / 512];
    int mytot = 0;
    for (int i = 0; i < PER; ++i) {
        int q = start + i;
        int t = (q < nq) ? g_qtot[q] : 0;
        tot_q[i] = t;
        mytot += t;
    }
    tsums[tid] = mytot;
    __syncthreads();

    for (int off = 1; off < 512; off <<= 1) {
        int v = (tid >= off) ? tsums[tid - off] : 0;
        __syncthreads();
        tsums[tid] += v;
        __syncthreads();
    }

    int run = (tid == 0) ? 0 : tsums[tid - 1];
    for (int i = 0; i < PER; ++i) {
        int q = start + i;
        if (q < nq) {
            g_offsets[q] = run;
            if (has_splits) splits[q] = (float)run;
            run += tot_q[i];
        }
    }
    if (tid == 511) {
        g_offsets[nq] = run;
        if (has_splits) splits[nq] = (float)run;
    }
}

// ---------------------------------------------------------------- fill ----
// Pure bit-scan: no geometry, no smem.
__global__ void fill_kernel(int nq, float* __restrict__ idx, int cap) {
    const int c = blockIdx.y;
    int q = blockIdx.x * blockDim.x + threadIdx.x;
    if (q >= nq) return;

    int w = g_offsets[q];
#pragma unroll
    for (int cc = 0; cc < CHUNKS; ++cc)
        if (cc < c) w += g_counts_c[cc * MAXN + q];

    const int jbase = c * CHSZ;
    for (int t = 0; t < WPC; ++t) {
        unsigned word = g_mask[(c * WPC + t) * nq + q];
        int j0 = jbase + t * 32;
        while (word) {
            int b = __ffs(word) - 1;
            word &= word - 1;
            if (w >= 0 && w < cap) idx[w] = (float)(j0 + b);
            ++w;
        }
    }
}

// -------------------------------------------------------------- launch ----
extern "C" void kernel_launch(void* const* d_in, const int* in_sizes, int n_in,
                              void* d_out, int out_size) {
    const float* data    = (const float*)d_in[0];
    const float* queries = (const float*)d_in[1];
    const float* radius  = (n_in >= 3 && in_sizes[2] >= 1) ? (const float*)d_in[2]
                                                           : nullptr;
    const int nd = in_sizes[0] / 3;
    const int nq = in_sizes[1] / 3;
    if (nd <= 0 || nq <= 0 || nd > MAXN || nq > MAXN) return;

    float* out = (float*)d_out;
    const int has_splits = (out_size >= nq + 1) ? 1 : 0;
    float* splits = has_splits ? (out + (out_size - (nq + 1))) : out;
    const int cap = has_splits ? (out_size - (nq + 1)) : out_size;

    const int qblocks = (nq + QBLK - 1) / QBLK;
    dim3 gridc(qblocks, (nd + CHSZ - 1) / CHSZ);

    thresh_kernel<<<1, 1>>>(radius);
    count_kernel <<<gridc, QBLK>>>(data, queries, nq, nd);
    reduce_kernel<<<qblocks, QBLK>>>(nq);
    scan_kernel  <<<1, 512>>>(splits, nq, has_splits);
    fill_kernel  <<<gridc, QBLK>>>(nq, out, cap);
}